// round 14
// baseline (speedup 1.0000x reference)
#include <cuda_runtime.h>
#include <cuda_fp16.h>
#include <cstdint>

// ============================================================================
// Problem constants
// ============================================================================
#define NROWS 8192
#define DDIM  1024
#define INV_T 14.285714285714285714f   // 1/0.07 ; also the static logit max M
#define K2E   20.60992915f             // INV_T * log2(e)
#define EXPC  14.0f                    // exponent shift: terms ~2^-6.6, max 2^14
#define C2    (EXPC - K2E)             // arg = d*K2E + C2
#define UNSHIFT 0x1p-14f

#define TILE 128
#define KCHUNK 64
#define NCHUNKS (DDIM / KCHUNK)   // 16
#define NBLK (NROWS / TILE)       // 64
#define NTILES (NBLK * NBLK)      // 4096
#define NTHREADS 128
#define STAGES 3
#define STAGE_BYTES 32768         // A(16KB) + B(16KB) per stage

// ============================================================================
// Device scratch (allocation-free rule: __device__ globals; zero-initialized)
// ============================================================================
__device__ __half g_imgn[NROWS * DDIM];
__device__ __half g_txtn[NROWS * DDIM];
__device__ float g_rowsum[NROWS];
__device__ float g_colsum[NROWS];
__device__ float g_diag;
__device__ unsigned int g_ctr;

// ============================================================================
// Helpers (sm_80-era instructions only)
// ============================================================================
__device__ __forceinline__ uint32_t smem_to_u32(const void* smem_ptr) {
    uint32_t addr;
    asm("{ .reg .u64 tmp; cvta.to.shared.u64 tmp, %1; cvt.u32.u64 %0, tmp; }"
        : "=r"(addr) : "l"(smem_ptr));
    return addr;
}

__device__ __forceinline__ void cp_async16(uint32_t saddr, const void* gptr) {
    asm volatile("cp.async.cg.shared.global [%0], [%1], 16;"
                 :: "r"(saddr), "l"(gptr) : "memory");
}
#define CP_ASYNC_COMMIT() asm volatile("cp.async.commit_group;" ::: "memory")
#define CP_ASYNC_WAIT1()  asm volatile("cp.async.wait_group 1;"  ::: "memory")

__device__ __forceinline__ void ldmatrix_x4(uint32_t r[4], uint32_t saddr) {
    asm volatile("ldmatrix.sync.aligned.m8n8.x4.shared.b16 {%0,%1,%2,%3}, [%4];"
                 : "=r"(r[0]), "=r"(r[1]), "=r"(r[2]), "=r"(r[3]) : "r"(saddr));
}

// fp16 inputs, fp32 accumulate (established fastest mma on this pipe)
__device__ __forceinline__ void mma_f16_f32(float c[4], const uint32_t a[4],
                                            uint32_t b0, uint32_t b1) {
    asm volatile(
        "mma.sync.aligned.m16n8k16.row.col.f32.f16.f16.f32 "
        "{%0,%1,%2,%3}, {%4,%5,%6,%7}, {%8,%9}, {%0,%1,%2,%3};"
        : "+f"(c[0]), "+f"(c[1]), "+f"(c[2]), "+f"(c[3])
        : "r"(a[0]), "r"(a[1]), "r"(a[2]), "r"(a[3]), "r"(b0), "r"(b1));
}

// pack two f32 into f16x2 (lo = a, hi = b)
__device__ __forceinline__ uint32_t pack_f16x2(float a, float b) {
    uint32_t r;
    asm("cvt.rn.f16x2.f32 %0, %1, %2;" : "=r"(r) : "f"(b), "f"(a));
    return r;
}
// two fp16 exp2 in one MUFU op
__device__ __forceinline__ uint32_t ex2_f16x2(uint32_t x) {
    uint32_t r;
    asm("ex2.approx.f16x2 %0, %1;" : "=r"(r) : "r"(x));
    return r;
}
__device__ __forceinline__ uint32_t hadd2u(uint32_t a, uint32_t b) {
    uint32_t r;
    asm("add.f16x2 %0, %1, %2;" : "=r"(r) : "r"(a), "r"(b));
    return r;
}
__device__ __forceinline__ float2 h2_to_f2(uint32_t h) {
    __half2 v = *reinterpret_cast<__half2*>(&h);
    return __half22float2(v);
}

#define SMEM_SWIZZLE_128B(byte_offset) \
    ((byte_offset) ^ (((byte_offset) >> 3) & 0x70))

// ============================================================================
// SMEM layout: 3 pipeline stages + small epilogue region (per CTA ~97.5KB)
// ============================================================================
#define SM_EPI      (STAGES * STAGE_BYTES)       // 98304
#define SM_ROWRED   (SM_EPI)                     // 128 floats
#define SM_COLRED   (SM_EPI + 512)               // 128 floats
#define SM_DIAG     (SM_EPI + 1024)              // 1 float
#define SM_LAST     (SM_EPI + 1028)              // 1 uint
#define SMEM_TOTAL  (SM_EPI + 1032)

// ============================================================================
// Kernel 1: normalize rows (eps-clamped) + pack to fp16. grid (8192,2), 128thr
// ============================================================================
__global__ void normalize_kernel(const float* __restrict__ img,
                                 const float* __restrict__ txt) {
    int row = blockIdx.x;
    const float* src = blockIdx.y ? txt : img;
    __half* dst = blockIdx.y ? g_txtn : g_imgn;
    int t = threadIdx.x;

    const float4* s4 = reinterpret_cast<const float4*>(src + (size_t)row * DDIM) + t * 2;
    float4 v0 = s4[0];
    float4 v1 = s4[1];
    float ss = v0.x * v0.x + v0.y * v0.y + v0.z * v0.z + v0.w * v0.w
             + v1.x * v1.x + v1.y * v1.y + v1.z * v1.z + v1.w * v1.w;
#pragma unroll
    for (int o = 16; o; o >>= 1) ss += __shfl_xor_sync(0xffffffffu, ss, o);

    __shared__ float ws[4];
    if ((t & 31) == 0) ws[t >> 5] = ss;
    __syncthreads();
    float tot = ws[0] + ws[1] + ws[2] + ws[3];
    float scale = 1.0f / fmaxf(sqrtf(tot), 1e-8f);

    __half2 h0 = __floats2half2_rn(v0.x * scale, v0.y * scale);
    __half2 h1 = __floats2half2_rn(v0.z * scale, v0.w * scale);
    __half2 h2 = __floats2half2_rn(v1.x * scale, v1.y * scale);
    __half2 h3 = __floats2half2_rn(v1.z * scale, v1.w * scale);
    uint4 o;
    o.x = *reinterpret_cast<uint32_t*>(&h0);
    o.y = *reinterpret_cast<uint32_t*>(&h1);
    o.z = *reinterpret_cast<uint32_t*>(&h2);
    o.w = *reinterpret_cast<uint32_t*>(&h3);
    reinterpret_cast<uint4*>(dst + (size_t)row * DDIM)[t] = o;
}

// ============================================================================
// Kernel 2: persistent fused GEMM + f16x2-exp + reductions + tail finalize
//   grid = 2 x #SMs, block 128 (4 warps: 2(M) x 2(N); warp tile 64x64)
//   Continuous 3-stage cp.async ring carried across tiles; chunk bodies for
//   k=14,15 are peeled and prefetch next tile's chunks 0,1 (hoisted pointers).
// ============================================================================
__global__ void __launch_bounds__(NTHREADS, 2) gemm_loss_kernel(float* __restrict__ out) {
    extern __shared__ char smem[];
    const uint32_t sb = smem_to_u32(smem);
    const int tid  = threadIdx.x;
    const int wid  = tid >> 5;
    const int lane = tid & 31;
    const int warp_m = wid & 1;
    const int warp_n = wid >> 1;
    const int G = gridDim.x;

    float* rowred = reinterpret_cast<float*>(smem + SM_ROWRED);
    float* colred = reinterpret_cast<float*>(smem + SM_COLRED);
    float* dsum   = reinterpret_cast<float*>(smem + SM_DIAG);
    unsigned int* lastf = reinterpret_cast<unsigned int*>(smem + SM_LAST);
    rowred[tid] = 0.0f;
    colred[tid] = 0.0f;
    if (tid == 0) dsum[0] = 0.0f;
    __syncthreads();

    // ---- per-thread load plan: 8 x 16B for A + 8 x 16B for B per chunk ----
    uint32_t sw_off[8];
    uint32_t gm_off[8];
#pragma unroll
    for (int i = 0; i < 8; i++) {
        int u = tid + NTHREADS * i;
        int row = u >> 3, c16 = u & 7;
        sw_off[i] = SMEM_SWIZZLE_128B((uint32_t)(row * 128 + c16 * 16));
        gm_off[i] = (uint32_t)(row * (DDIM / 8) + c16);
    }

    // ---- per-thread ldmatrix address components ----
    const uint32_t aRowByte = (uint32_t)((warp_m * 64 + (lane & 15)) * 128);
    const uint32_t aXor = (uint32_t)((lane & 7) << 4);
    const uint32_t aKB  = (uint32_t)((lane >> 4) * 16);
    const uint32_t bRowByte =
        (uint32_t)((warp_n * 64 + (lane & 7) + ((lane >> 4) & 1) * 8) * 128);
    const uint32_t bXor = (uint32_t)((lane & 7) << 4);
    const uint32_t bKB  = (uint32_t)(((lane >> 3) & 1) * 16);

    const uint4* baseA = reinterpret_cast<const uint4*>(g_imgn);
    const uint4* baseB = reinterpret_cast<const uint4*>(g_txtn);
    const int rowU4 = DDIM / 8;

    float acc[4][8][4];
#pragma unroll
    for (int mt = 0; mt < 4; mt++)
#pragma unroll
        for (int nt = 0; nt < 8; nt++)
#pragma unroll
            for (int e = 0; e < 4; e++) acc[mt][nt][e] = 0.0f;

    int slot_c = 0;   // stage ring carried across tiles

    // one chunk body: consume slot_c, prefetch (pA,pB) into slot_c+2, advance
    auto chunk_body = [&](const uint4* pA, const uint4* pB, bool pf) {
        CP_ASYNC_WAIT1();
        __syncthreads();
        const uint32_t sAs = sb + slot_c * STAGE_BYTES;
        const uint32_t sBs = sAs + 16384;
        const int slot_p = slot_c + 2 >= STAGES ? slot_c + 2 - STAGES : slot_c + 2;
        const uint32_t sAp = sb + slot_p * STAGE_BYTES;
        const uint32_t sBp = sAp + 16384;
#pragma unroll
        for (int ks = 0; ks < 4; ks++) {
            uint32_t a[4][4];
#pragma unroll
            for (int mt = 0; mt < 4; mt++)
                ldmatrix_x4(a[mt], sAs + aRowByte + (uint32_t)(mt * 16 * 128)
                            + (((uint32_t)(ks * 32) + aKB) ^ aXor));
            uint32_t bf[4][4];
#pragma unroll
            for (int p = 0; p < 4; p++)
                ldmatrix_x4(bf[p], sBs + bRowByte + (uint32_t)(p * 16 * 128)
                            + (((uint32_t)(ks * 32) + bKB) ^ bXor));
            if (pf) {
                cp_async16(sAp + sw_off[ks], pA + gm_off[ks]);
                cp_async16(sAp + sw_off[ks + 4], pA + gm_off[ks + 4]);
                cp_async16(sBp + sw_off[ks], pB + gm_off[ks]);
                cp_async16(sBp + sw_off[ks + 4], pB + gm_off[ks + 4]);
            }
#pragma unroll
            for (int mt = 0; mt < 4; mt++)
#pragma unroll
                for (int nt = 0; nt < 8; nt++) {
                    const uint32_t b0 = bf[nt >> 1][(nt & 1) * 2 + 0];
                    const uint32_t b1 = bf[nt >> 1][(nt & 1) * 2 + 1];
                    mma_f16_f32(acc[mt][nt], a[mt], b0, b1);
                }
        }
        CP_ASYNC_COMMIT();
        slot_c = slot_c + 1 >= STAGES ? 0 : slot_c + 1;
    };

    // ---- prologue for first tile ----
    const int t0 = blockIdx.x;
    if (t0 < NTILES) {
        const uint4* Ag0 = baseA + (size_t)(t0 >> 6) * TILE * rowU4;
        const uint4* Bg0 = baseB + (size_t)(t0 & 63) * TILE * rowU4;
#pragma unroll
        for (int s = 0; s < 2; s++) {
            uint32_t sA = sb + s * STAGE_BYTES;
            uint32_t sB = sA + 16384;
#pragma unroll
            for (int i = 0; i < 8; i++) {
                cp_async16(sA + sw_off[i], Ag0 + gm_off[i] + s * 8);
                cp_async16(sB + sw_off[i], Bg0 + gm_off[i] + s * 8);
            }
            CP_ASYNC_COMMIT();
        }
    }

    for (int t = t0; t < NTILES; t += G) {
        const int bi = t >> 6;
        const int bj = t & 63;
        const uint4* Ag = baseA + (size_t)bi * TILE * rowU4;
        const uint4* Bg = baseB + (size_t)bj * TILE * rowU4;
        const int t2 = t + G;
        const bool nvalid = (t2 < NTILES);
        const uint4* Ag2 = nvalid ? baseA + (size_t)(t2 >> 6) * TILE * rowU4 : Ag;
        const uint4* Bg2 = nvalid ? baseB + (size_t)(t2 & 63) * TILE * rowU4 : Bg;

        // k = 0..13: in-tile prefetch (pointer = simple offset add, no selects)
#pragma unroll 1
        for (int k = 0; k < NCHUNKS - 2; k++) {
            chunk_body(Ag + (k + 2) * 8, Bg + (k + 2) * 8, true);
        }
        // k = 14, 15: prefetch next tile's chunks 0, 1
        chunk_body(Ag2, Bg2, nvalid);
        chunk_body(Ag2 + 8, Bg2 + 8, nvalid);

        // ---- epilogue (runs under next tile's in-flight loads) ----
        const int g  = lane >> 2;
        const int t4 = lane & 3;
        const bool diagcta = (bi == bj);
        uint32_t rs0h[4] = {0, 0, 0, 0}, rs1h[4] = {0, 0, 0, 0};
        uint32_t colh[8] = {0, 0, 0, 0, 0, 0, 0, 0};
        float dloc = 0.0f;

#pragma unroll
        for (int mt = 0; mt < 4; mt++) {
#pragma unroll
            for (int nt = 0; nt < 8; nt++) {
                float d0 = acc[mt][nt][0], d1 = acc[mt][nt][1];
                float d2 = acc[mt][nt][2], d3 = acc[mt][nt][3];
                acc[mt][nt][0] = 0.0f; acc[mt][nt][1] = 0.0f;
                acc[mt][nt][2] = 0.0f; acc[mt][nt][3] = 0.0f;
                float a0 = fmaf(d0, K2E, C2);
                float a1 = fmaf(d1, K2E, C2);
                float a2 = fmaf(d2, K2E, C2);
                float a3 = fmaf(d3, K2E, C2);
                uint32_t e01 = ex2_f16x2(pack_f16x2(a0, a1));
                uint32_t e23 = ex2_f16x2(pack_f16x2(a2, a3));
                rs0h[mt] = hadd2u(rs0h[mt], e01);
                rs1h[mt] = hadd2u(rs1h[mt], e23);
                colh[nt] = hadd2u(colh[nt], hadd2u(e01, e23));
                if (diagcta) {
                    int r0 = warp_m * 64 + mt * 16 + g;
                    int c0 = warp_n * 64 + nt * 8 + 2 * t4;
                    if (r0 == c0)         dloc += d0;
                    if (r0 == c0 + 1)     dloc += d1;
                    if (r0 + 8 == c0)     dloc += d2;
                    if (r0 + 8 == c0 + 1) dloc += d3;
                }
            }
        }

#pragma unroll
        for (int mt = 0; mt < 4; mt++) {
            float2 f0 = h2_to_f2(rs0h[mt]);
            float2 f1 = h2_to_f2(rs1h[mt]);
            float v0 = f0.x + f0.y;
            float v1 = f1.x + f1.y;
            v0 += __shfl_xor_sync(0xffffffffu, v0, 1);
            v0 += __shfl_xor_sync(0xffffffffu, v0, 2);
            v1 += __shfl_xor_sync(0xffffffffu, v1, 1);
            v1 += __shfl_xor_sync(0xffffffffu, v1, 2);
            if (t4 == 0) {
                int r = warp_m * 64 + mt * 16 + g;
                atomicAdd(&rowred[r], v0);
                atomicAdd(&rowred[r + 8], v1);
            }
        }
#pragma unroll
        for (int nt = 0; nt < 8; nt++) {
            float2 fc = h2_to_f2(colh[nt]);
            float u0 = fc.x, u1 = fc.y;
            u0 += __shfl_xor_sync(0xffffffffu, u0, 4);
            u0 += __shfl_xor_sync(0xffffffffu, u0, 8);
            u0 += __shfl_xor_sync(0xffffffffu, u0, 16);
            u1 += __shfl_xor_sync(0xffffffffu, u1, 4);
            u1 += __shfl_xor_sync(0xffffffffu, u1, 8);
            u1 += __shfl_xor_sync(0xffffffffu, u1, 16);
            if (lane < 4) {
                int c = warp_n * 64 + nt * 8 + 2 * t4;
                atomicAdd(&colred[c], u0);
                atomicAdd(&colred[c + 1], u1);
            }
        }
        if (diagcta && dloc != 0.0f) atomicAdd(dsum, dloc);

        __syncthreads();
        atomicAdd(&g_rowsum[bi * TILE + tid], rowred[tid] * UNSHIFT);
        atomicAdd(&g_colsum[bj * TILE + tid], colred[tid] * UNSHIFT);
        rowred[tid] = 0.0f;
        colred[tid] = 0.0f;
        if (diagcta && tid == 0) atomicAdd(&g_diag, dsum[0] * INV_T);
        if (tid == 0) dsum[0] = 0.0f;
        __syncthreads();
    }

    // ---- last-CTA finalize + reset (graph-replay safe) ----
    __threadfence();
    if (tid == 0) lastf[0] = atomicAdd(&g_ctr, 1u);
    __syncthreads();
    if (lastf[0] == G - 1) {
        float accl = 0.0f;
        for (int i = tid; i < NROWS; i += NTHREADS)
            accl += logf(g_rowsum[i]) + logf(g_colsum[i]);
#pragma unroll
        for (int o = 16; o; o >>= 1) accl += __shfl_xor_sync(0xffffffffu, accl, o);
        if (lane == 0) colred[wid] = accl;
        __syncthreads();
        if (tid == 0) {
            float v = colred[0] + colred[1] + colred[2] + colred[3];
            out[0] = INV_T + 0.5f * v / (float)NROWS - g_diag / (float)NROWS;
            g_diag = 0.0f;
            g_ctr = 0u;
        }
        __syncthreads();
        for (int i = tid; i < NROWS; i += NTHREADS) {
            g_rowsum[i] = 0.0f;
            g_colsum[i] = 0.0f;
        }
    }
}

// ============================================================================
// Launch
// ============================================================================
extern "C" void kernel_launch(void* const* d_in, const int* in_sizes, int n_in,
                              void* d_out, int out_size) {
    const float* img = (const float*)d_in[0];
    const float* txt = (const float*)d_in[1];
    float* out = (float*)d_out;

    int nsm = 148;
    cudaDeviceGetAttribute(&nsm, cudaDevAttrMultiProcessorCount, 0);

    cudaFuncSetAttribute(gemm_loss_kernel,
                         cudaFuncAttributeMaxDynamicSharedMemorySize, SMEM_TOTAL);

    normalize_kernel<<<dim3(NROWS, 2), 128>>>(img, txt);
    gemm_loss_kernel<<<nsm * 2, NTHREADS, SMEM_TOTAL>>>(out);
}

// round 15
// speedup vs baseline: 1.0112x; 1.0112x over previous
#include <cuda_runtime.h>
#include <cuda_fp16.h>
#include <cstdint>

// ============================================================================
// Problem constants
// ============================================================================
#define NROWS 8192
#define DDIM  1024
#define INV_T 14.285714285714285714f   // 1/0.07 ; also the static logit max M
#define K2E   20.60992915f             // INV_T * log2(e)
#define EXPC  14.0f                    // exponent shift: terms ~2^-6.6, max 2^14
#define C2    (EXPC - K2E)             // arg = d*K2E + C2
#define UNSHIFT 0x1p-14f

#define TILE 128
#define KCHUNK 64
#define NCHUNKS (DDIM / KCHUNK)   // 16
#define NBLK (NROWS / TILE)       // 64
#define NCTAS (NBLK * NBLK)       // 4096
#define NTHREADS 128
#define STAGES 3
#define STAGE_BYTES 32768         // A(16KB) + B(16KB) per stage

// ============================================================================
// Device scratch (allocation-free rule: __device__ globals; zero-initialized)
// ============================================================================
__device__ __half g_imgn[NROWS * DDIM];
__device__ __half g_txtn[NROWS * DDIM];
__device__ float g_rowsum[NROWS];
__device__ float g_colsum[NROWS];
__device__ float g_diag;
__device__ unsigned int g_ctr;

// ============================================================================
// Helpers (sm_80-era instructions only)
// ============================================================================
__device__ __forceinline__ uint32_t smem_to_u32(const void* smem_ptr) {
    uint32_t addr;
    asm("{ .reg .u64 tmp; cvta.to.shared.u64 tmp, %1; cvt.u32.u64 %0, tmp; }"
        : "=r"(addr) : "l"(smem_ptr));
    return addr;
}

__device__ __forceinline__ void cp_async16(uint32_t saddr, const void* gptr) {
    asm volatile("cp.async.cg.shared.global [%0], [%1], 16;"
                 :: "r"(saddr), "l"(gptr) : "memory");
}
#define CP_ASYNC_COMMIT() asm volatile("cp.async.commit_group;" ::: "memory")
#define CP_ASYNC_WAIT1()  asm volatile("cp.async.wait_group 1;"  ::: "memory")

// producer/consumer named barriers (avoid barrier 0 = __syncthreads)
#define NBAR_ARRIVE(b) asm volatile("bar.arrive %0, 256;" :: "r"(b) : "memory")
#define NBAR_SYNC(b)   asm volatile("bar.sync %0, 256;"   :: "r"(b) : "memory")

__device__ __forceinline__ void ldmatrix_x4(uint32_t r[4], uint32_t saddr) {
    asm volatile("ldmatrix.sync.aligned.m8n8.x4.shared.b16 {%0,%1,%2,%3}, [%4];"
                 : "=r"(r[0]), "=r"(r[1]), "=r"(r[2]), "=r"(r[3]) : "r"(saddr));
}

// fp16 inputs, fp32 accumulate (established fastest mma on this pipe)
__device__ __forceinline__ void mma_f16_f32(float c[4], const uint32_t a[4],
                                            uint32_t b0, uint32_t b1) {
    asm volatile(
        "mma.sync.aligned.m16n8k16.row.col.f32.f16.f16.f32 "
        "{%0,%1,%2,%3}, {%4,%5,%6,%7}, {%8,%9}, {%0,%1,%2,%3};"
        : "+f"(c[0]), "+f"(c[1]), "+f"(c[2]), "+f"(c[3])
        : "r"(a[0]), "r"(a[1]), "r"(a[2]), "r"(a[3]), "r"(b0), "r"(b1));
}

// pack two f32 into f16x2 (lo = a, hi = b)
__device__ __forceinline__ uint32_t pack_f16x2(float a, float b) {
    uint32_t r;
    asm("cvt.rn.f16x2.f32 %0, %1, %2;" : "=r"(r) : "f"(b), "f"(a));
    return r;
}
// two fp16 exp2 in one MUFU op
__device__ __forceinline__ uint32_t ex2_f16x2(uint32_t x) {
    uint32_t r;
    asm("ex2.approx.f16x2 %0, %1;" : "=r"(r) : "r"(x));
    return r;
}
__device__ __forceinline__ uint32_t hadd2u(uint32_t a, uint32_t b) {
    uint32_t r;
    asm("add.f16x2 %0, %1, %2;" : "=r"(r) : "r"(a), "r"(b));
    return r;
}
__device__ __forceinline__ float2 h2_to_f2(uint32_t h) {
    __half2 v = *reinterpret_cast<__half2*>(&h);
    return __half22float2(v);
}

#define SMEM_SWIZZLE_128B(byte_offset) \
    ((byte_offset) ^ (((byte_offset) >> 3) & 0x70))

// ============================================================================
// SMEM layout: 3 pipeline stages + small epilogue region (per CTA ~97.5KB)
// ============================================================================
#define SM_EPI      (STAGES * STAGE_BYTES)       // 98304
#define SM_ROWRED   (SM_EPI)                     // 128 floats
#define SM_COLRED   (SM_EPI + 512)               // 128 floats
#define SM_DIAG     (SM_EPI + 1024)              // 1 float
#define SM_LAST     (SM_EPI + 1028)              // 1 uint
#define SMEM_TOTAL  (SM_EPI + 1032)

// ============================================================================
// Kernel 1: normalize rows (eps-clamped) + pack to fp16. grid (8192,2), 128thr
// ============================================================================
__global__ void normalize_kernel(const float* __restrict__ img,
                                 const float* __restrict__ txt) {
    int row = blockIdx.x;
    const float* src = blockIdx.y ? txt : img;
    __half* dst = blockIdx.y ? g_txtn : g_imgn;
    int t = threadIdx.x;

    const float4* s4 = reinterpret_cast<const float4*>(src + (size_t)row * DDIM) + t * 2;
    float4 v0 = s4[0];
    float4 v1 = s4[1];
    float ss = v0.x * v0.x + v0.y * v0.y + v0.z * v0.z + v0.w * v0.w
             + v1.x * v1.x + v1.y * v1.y + v1.z * v1.z + v1.w * v1.w;
#pragma unroll
    for (int o = 16; o; o >>= 1) ss += __shfl_xor_sync(0xffffffffu, ss, o);

    __shared__ float ws[4];
    if ((t & 31) == 0) ws[t >> 5] = ss;
    __syncthreads();
    float tot = ws[0] + ws[1] + ws[2] + ws[3];
    float scale = 1.0f / fmaxf(sqrtf(tot), 1e-8f);

    __half2 h0 = __floats2half2_rn(v0.x * scale, v0.y * scale);
    __half2 h1 = __floats2half2_rn(v0.z * scale, v0.w * scale);
    __half2 h2 = __floats2half2_rn(v1.x * scale, v1.y * scale);
    __half2 h3 = __floats2half2_rn(v1.z * scale, v1.w * scale);
    uint4 o;
    o.x = *reinterpret_cast<uint32_t*>(&h0);
    o.y = *reinterpret_cast<uint32_t*>(&h1);
    o.z = *reinterpret_cast<uint32_t*>(&h2);
    o.w = *reinterpret_cast<uint32_t*>(&h3);
    reinterpret_cast<uint4*>(dst + (size_t)row * DDIM)[t] = o;
}

// ============================================================================
// Kernel 2: fused GEMM + f16x2-exp + reductions + tail finalize
//   grid (64,64), block 128 (4 warps: 2(M) x 2(N); warp tile 64x64)
//   CTA tile 128x128, 3-stage cp.async, 2 CTAs/SM, split named barriers,
//   B-half interleaved inner loop (shorter LDSM->HMMA critical path)
// ============================================================================
__global__ void __launch_bounds__(NTHREADS, 2) gemm_loss_kernel(float* __restrict__ out) {
    extern __shared__ char smem[];
    const uint32_t sb = smem_to_u32(smem);
    const int tid  = threadIdx.x;
    const int wid  = tid >> 5;
    const int lane = tid & 31;
    const int warp_m = wid & 1;
    const int warp_n = wid >> 1;
    const int bi = blockIdx.y;
    const int bj = blockIdx.x;

    float* rowred = reinterpret_cast<float*>(smem + SM_ROWRED);
    float* colred = reinterpret_cast<float*>(smem + SM_COLRED);
    float* dsum   = reinterpret_cast<float*>(smem + SM_DIAG);
    unsigned int* lastf = reinterpret_cast<unsigned int*>(smem + SM_LAST);
    rowred[tid] = 0.0f;
    colred[tid] = 0.0f;
    if (tid == 0) dsum[0] = 0.0f;

    // ---- global load plan per stage: A 8 x 16B + B 8 x 16B per thread ----
    const uint4* Ag = reinterpret_cast<const uint4*>(g_imgn) + (size_t)bi * TILE * (DDIM / 8);
    const uint4* Bg = reinterpret_cast<const uint4*>(g_txtn) + (size_t)bj * TILE * (DDIM / 8);

    uint32_t sw_off[8];
    uint32_t gm_off[8];
#pragma unroll
    for (int i = 0; i < 8; i++) {
        int u = tid + NTHREADS * i;
        int row = u >> 3, c16 = u & 7;
        sw_off[i] = SMEM_SWIZZLE_128B((uint32_t)(row * 128 + c16 * 16));
        gm_off[i] = (uint32_t)(row * (DDIM / 8) + c16);
    }

    // ---- prologue: stages 0 and 1 ----
#pragma unroll
    for (int s = 0; s < 2; s++) {
        uint32_t sA = sb + s * STAGE_BYTES;
        uint32_t sB = sA + 16384;
#pragma unroll
        for (int i = 0; i < 8; i++) {
            cp_async16(sA + sw_off[i], Ag + gm_off[i] + s * 8);
            cp_async16(sB + sw_off[i], Bg + gm_off[i] + s * 8);
        }
        CP_ASYNC_COMMIT();
    }

    // ---- per-thread ldmatrix address components ----
    const uint32_t aRowByte = (uint32_t)((warp_m * 64 + (lane & 15)) * 128);
    const uint32_t aXor = (uint32_t)((lane & 7) << 4);
    const uint32_t aKB  = (uint32_t)((lane >> 4) * 16);
    const uint32_t bRowByte =
        (uint32_t)((warp_n * 64 + (lane & 7) + ((lane >> 4) & 1) * 8) * 128);
    const uint32_t bXor = (uint32_t)((lane & 7) << 4);
    const uint32_t bKB  = (uint32_t)(((lane >> 3) & 1) * 16);

    float acc[4][8][4];
#pragma unroll
    for (int mt = 0; mt < 4; mt++)
#pragma unroll
        for (int nt = 0; nt < 8; nt++)
#pragma unroll
            for (int e = 0; e < 4; e++) acc[mt][nt][e] = 0.0f;

    // ---- mainloop: split barriers + B-half interleaved k-steps ----
    int slot_c = 0;
#pragma unroll 1
    for (int k = 0; k < NCHUNKS; k++) {
        CP_ASYNC_WAIT1();
        if (k == 0) {
            __syncthreads();
        } else {
            NBAR_SYNC(1 + ((k + 1) & 1));
        }

        const uint32_t sAs = sb + slot_c * STAGE_BYTES;
        const uint32_t sBs = sAs + 16384;
        const int kp = k + 2;
        const int slot_p = slot_c + 2 >= STAGES ? slot_c + 2 - STAGES : slot_c + 2;
        const uint32_t sAp = sb + slot_p * STAGE_BYTES;
        const uint32_t sBp = sAp + 16384;
        const bool pf = (kp < NCHUNKS);

#pragma unroll
        for (int ks = 0; ks < 4; ks++) {
            const uint32_t kby = (uint32_t)(ks * 32);
            uint32_t a[4][4];
#pragma unroll
            for (int mt = 0; mt < 4; mt++)
                ldmatrix_x4(a[mt], sAs + aRowByte + (uint32_t)(mt * 16 * 128)
                            + ((kby + aKB) ^ aXor));
            // B first half (nt 0..3)
            uint32_t bf0[2][4];
#pragma unroll
            for (int p = 0; p < 2; p++)
                ldmatrix_x4(bf0[p], sBs + bRowByte + (uint32_t)(p * 16 * 128)
                            + ((kby + bKB) ^ bXor));
            // HMMA on first half while second half loads
#pragma unroll
            for (int mt = 0; mt < 4; mt++)
#pragma unroll
                for (int q = 0; q < 4; q++) {
                    const uint32_t b0 = bf0[q >> 1][(q & 1) * 2 + 0];
                    const uint32_t b1 = bf0[q >> 1][(q & 1) * 2 + 1];
                    mma_f16_f32(acc[mt][q], a[mt], b0, b1);
                }
            // B second half (nt 4..7)
            uint32_t bf1[2][4];
#pragma unroll
            for (int p = 0; p < 2; p++)
                ldmatrix_x4(bf1[p], sBs + bRowByte + (uint32_t)((p + 2) * 16 * 128)
                            + ((kby + bKB) ^ bXor));
            // all LDSM reads of this chunk's slot done -> signal consumers
            if (ks == 3) NBAR_ARRIVE(1 + (k & 1));
            if (pf) {
                cp_async16(sAp + sw_off[ks], Ag + gm_off[ks] + kp * 8);
                cp_async16(sAp + sw_off[ks + 4], Ag + gm_off[ks + 4] + kp * 8);
                cp_async16(sBp + sw_off[ks], Bg + gm_off[ks] + kp * 8);
                cp_async16(sBp + sw_off[ks + 4], Bg + gm_off[ks + 4] + kp * 8);
            }
#pragma unroll
            for (int mt = 0; mt < 4; mt++)
#pragma unroll
                for (int q = 0; q < 4; q++) {
                    const uint32_t b0 = bf1[q >> 1][(q & 1) * 2 + 0];
                    const uint32_t b1 = bf1[q >> 1][(q & 1) * 2 + 1];
                    mma_f16_f32(acc[mt][q + 4], a[mt], b0, b1);
                }
        }
        CP_ASYNC_COMMIT();
        slot_c = slot_c + 1 >= STAGES ? 0 : slot_c + 1;
    }

    // ---- epilogue: f16x2 exp + reductions ----
    const int g  = lane >> 2;    // 0..7 : row within 8
    const int t4 = lane & 3;     // 0..3 : column pair selector
    const bool diagcta = (bi == bj);
    uint32_t rs0h[4] = {0, 0, 0, 0}, rs1h[4] = {0, 0, 0, 0};
    uint32_t colh[8] = {0, 0, 0, 0, 0, 0, 0, 0};
    float dloc = 0.0f;

#pragma unroll
    for (int mt = 0; mt < 4; mt++) {
#pragma unroll
        for (int nt = 0; nt < 8; nt++) {
            float d0 = acc[mt][nt][0], d1 = acc[mt][nt][1];
            float d2 = acc[mt][nt][2], d3 = acc[mt][nt][3];
            float a0 = fmaf(d0, K2E, C2);
            float a1 = fmaf(d1, K2E, C2);
            float a2 = fmaf(d2, K2E, C2);
            float a3 = fmaf(d3, K2E, C2);
            uint32_t e01 = ex2_f16x2(pack_f16x2(a0, a1));
            uint32_t e23 = ex2_f16x2(pack_f16x2(a2, a3));
            rs0h[mt] = hadd2u(rs0h[mt], e01);
            rs1h[mt] = hadd2u(rs1h[mt], e23);
            colh[nt] = hadd2u(colh[nt], hadd2u(e01, e23));
            if (diagcta) {
                int r0 = warp_m * 64 + mt * 16 + g;
                int c0 = warp_n * 64 + nt * 8 + 2 * t4;
                if (r0 == c0)         dloc += d0;
                if (r0 == c0 + 1)     dloc += d1;
                if (r0 + 8 == c0)     dloc += d2;
                if (r0 + 8 == c0 + 1) dloc += d3;
            }
        }
    }

#pragma unroll
    for (int mt = 0; mt < 4; mt++) {
        float2 f0 = h2_to_f2(rs0h[mt]);
        float2 f1 = h2_to_f2(rs1h[mt]);
        float v0 = f0.x + f0.y;
        float v1 = f1.x + f1.y;
        v0 += __shfl_xor_sync(0xffffffffu, v0, 1);
        v0 += __shfl_xor_sync(0xffffffffu, v0, 2);
        v1 += __shfl_xor_sync(0xffffffffu, v1, 1);
        v1 += __shfl_xor_sync(0xffffffffu, v1, 2);
        if (t4 == 0) {
            int r = warp_m * 64 + mt * 16 + g;
            atomicAdd(&rowred[r], v0);
            atomicAdd(&rowred[r + 8], v1);
        }
    }
#pragma unroll
    for (int nt = 0; nt < 8; nt++) {
        float2 fc = h2_to_f2(colh[nt]);
        float u0 = fc.x, u1 = fc.y;
        u0 += __shfl_xor_sync(0xffffffffu, u0, 4);
        u0 += __shfl_xor_sync(0xffffffffu, u0, 8);
        u0 += __shfl_xor_sync(0xffffffffu, u0, 16);
        u1 += __shfl_xor_sync(0xffffffffu, u1, 4);
        u1 += __shfl_xor_sync(0xffffffffu, u1, 8);
        u1 += __shfl_xor_sync(0xffffffffu, u1, 16);
        if (lane < 4) {
            int c = warp_n * 64 + nt * 8 + 2 * t4;
            atomicAdd(&colred[c], u0);
            atomicAdd(&colred[c + 1], u1);
        }
    }
    if (diagcta && dloc != 0.0f) atomicAdd(dsum, dloc);

    __syncthreads();
    atomicAdd(&g_rowsum[bi * TILE + tid], rowred[tid] * UNSHIFT);
    atomicAdd(&g_colsum[bj * TILE + tid], colred[tid] * UNSHIFT);
    if (diagcta && tid == 0) atomicAdd(&g_diag, dsum[0] * INV_T);

    // ---- last-CTA finalize + reset (graph-replay safe) ----
    __threadfence();
    if (tid == 0) lastf[0] = atomicAdd(&g_ctr, 1u);
    __syncthreads();
    if (lastf[0] == NCTAS - 1) {
        float accl = 0.0f;
        for (int i = tid; i < NROWS; i += NTHREADS)
            accl += logf(g_rowsum[i]) + logf(g_colsum[i]);
#pragma unroll
        for (int o = 16; o; o >>= 1) accl += __shfl_xor_sync(0xffffffffu, accl, o);
        if (lane == 0) colred[wid] = accl;
        __syncthreads();
        if (tid == 0) {
            float v = colred[0] + colred[1] + colred[2] + colred[3];
            out[0] = INV_T + 0.5f * v / (float)NROWS - g_diag / (float)NROWS;
            g_diag = 0.0f;
            g_ctr = 0u;
        }
        __syncthreads();
        for (int i = tid; i < NROWS; i += NTHREADS) {
            g_rowsum[i] = 0.0f;
            g_colsum[i] = 0.0f;
        }
    }
}

// ============================================================================
// Launch
// ============================================================================
extern "C" void kernel_launch(void* const* d_in, const int* in_sizes, int n_in,
                              void* d_out, int out_size) {
    const float* img = (const float*)d_in[0];
    const float* txt = (const float*)d_in[1];
    float* out = (float*)d_out;

    cudaFuncSetAttribute(gemm_loss_kernel,
                         cudaFuncAttributeMaxDynamicSharedMemorySize, SMEM_TOTAL);

    normalize_kernel<<<dim3(NROWS, 2), 128>>>(img, txt);
    gemm_loss_kernel<<<dim3(NBLK, NBLK), NTHREADS, SMEM_TOTAL>>>(out);
}

// round 16
// speedup vs baseline: 1.0971x; 1.0850x over previous
#include <cuda_runtime.h>
#include <cuda_fp16.h>
#include <cstdint>

// ============================================================================
// Problem constants
// ============================================================================
#define NROWS 8192
#define DDIM  1024
#define INV_T 14.285714285714285714f   // 1/0.07 ; also the static logit max M
#define K2E   20.60992915f             // INV_T * log2(e)
#define EXPC  14.0f                    // exponent shift: terms ~2^-6.6, max 2^14
#define C2    (EXPC - K2E)             // arg = d*K2E + C2
#define UNSHIFT 0x1p-14f

#define TILE 128
#define KCHUNK 64
#define NCHUNKS (DDIM / KCHUNK)   // 16
#define NBLK (NROWS / TILE)       // 64
#define NCTAS (NBLK * NBLK)       // 4096
#define NTHREADS 128
#define STAGES 3
#define STAGE_BYTES 32768         // A(16KB) + B(16KB) per stage

// ============================================================================
// Device scratch (allocation-free rule: __device__ globals; zero-initialized)
// ============================================================================
__device__ __half g_imgn[NROWS * DDIM];
__device__ __half g_txtn[NROWS * DDIM];
__device__ float g_rowsum[NROWS];
__device__ float g_colsum[NROWS];
__device__ float g_diag;
__device__ unsigned int g_ctr;

// ============================================================================
// Helpers (sm_80-era instructions only)
// ============================================================================
__device__ __forceinline__ uint32_t smem_to_u32(const void* smem_ptr) {
    uint32_t addr;
    asm("{ .reg .u64 tmp; cvta.to.shared.u64 tmp, %1; cvt.u32.u64 %0, tmp; }"
        : "=r"(addr) : "l"(smem_ptr));
    return addr;
}

__device__ __forceinline__ void cp_async16(uint32_t saddr, const void* gptr) {
    asm volatile("cp.async.cg.shared.global [%0], [%1], 16;"
                 :: "r"(saddr), "l"(gptr) : "memory");
}
#define CP_ASYNC_COMMIT() asm volatile("cp.async.commit_group;" ::: "memory")
#define CP_ASYNC_WAIT1()  asm volatile("cp.async.wait_group 1;"  ::: "memory")

// producer/consumer named barriers (avoid barrier 0 = __syncthreads)
#define NBAR_ARRIVE(b) asm volatile("bar.arrive %0, 256;" :: "r"(b) : "memory")
#define NBAR_SYNC(b)   asm volatile("bar.sync %0, 256;"   :: "r"(b) : "memory")

__device__ __forceinline__ void ldmatrix_x4(uint32_t r[4], uint32_t saddr) {
    asm volatile("ldmatrix.sync.aligned.m8n8.x4.shared.b16 {%0,%1,%2,%3}, [%4];"
                 : "=r"(r[0]), "=r"(r[1]), "=r"(r[2]), "=r"(r[3]) : "r"(saddr));
}

// fp16 inputs, fp32 accumulate (established fastest mma on this pipe)
__device__ __forceinline__ void mma_f16_f32(float c[4], const uint32_t a[4],
                                            uint32_t b0, uint32_t b1) {
    asm volatile(
        "mma.sync.aligned.m16n8k16.row.col.f32.f16.f16.f32 "
        "{%0,%1,%2,%3}, {%4,%5,%6,%7}, {%8,%9}, {%0,%1,%2,%3};"
        : "+f"(c[0]), "+f"(c[1]), "+f"(c[2]), "+f"(c[3])
        : "r"(a[0]), "r"(a[1]), "r"(a[2]), "r"(a[3]), "r"(b0), "r"(b1));
}

// pack two f32 into f16x2 (lo = a, hi = b)
__device__ __forceinline__ uint32_t pack_f16x2(float a, float b) {
    uint32_t r;
    asm("cvt.rn.f16x2.f32 %0, %1, %2;" : "=r"(r) : "f"(b), "f"(a));
    return r;
}
// two fp16 exp2 in one MUFU op
__device__ __forceinline__ uint32_t ex2_f16x2(uint32_t x) {
    uint32_t r;
    asm("ex2.approx.f16x2 %0, %1;" : "=r"(r) : "r"(x));
    return r;
}
__device__ __forceinline__ uint32_t hadd2u(uint32_t a, uint32_t b) {
    uint32_t r;
    asm("add.f16x2 %0, %1, %2;" : "=r"(r) : "r"(a), "r"(b));
    return r;
}
__device__ __forceinline__ float2 h2_to_f2(uint32_t h) {
    __half2 v = *reinterpret_cast<__half2*>(&h);
    return __half22float2(v);
}

#define SMEM_SWIZZLE_128B(byte_offset) \
    ((byte_offset) ^ (((byte_offset) >> 3) & 0x70))

// ============================================================================
// SMEM layout: 3 pipeline stages + small epilogue region (per CTA ~97.5KB)
// ============================================================================
#define SM_EPI      (STAGES * STAGE_BYTES)       // 98304
#define SM_ROWRED   (SM_EPI)                     // 128 floats
#define SM_COLRED   (SM_EPI + 512)               // 128 floats
#define SM_DIAG     (SM_EPI + 1024)              // 1 float
#define SM_LAST     (SM_EPI + 1028)              // 1 uint
#define SMEM_TOTAL  (SM_EPI + 1032)

// ============================================================================
// Kernel 1: normalize 2 rows/block (eps-clamped) + pack to fp16
//   grid (4096, 2), block 256 (two independent 128-thread row groups)
// ============================================================================
__global__ void normalize_kernel(const float* __restrict__ img,
                                 const float* __restrict__ txt) {
    int grp = threadIdx.x >> 7;               // 0..1 : row within block
    int row = blockIdx.x * 2 + grp;
    const float* src = blockIdx.y ? txt : img;
    __half* dst = blockIdx.y ? g_txtn : g_imgn;
    int t = threadIdx.x & 127;

    const float4* s4 = reinterpret_cast<const float4*>(src + (size_t)row * DDIM) + t * 2;
    float4 v0 = s4[0];
    float4 v1 = s4[1];
    float ss = v0.x * v0.x + v0.y * v0.y + v0.z * v0.z + v0.w * v0.w
             + v1.x * v1.x + v1.y * v1.y + v1.z * v1.z + v1.w * v1.w;
#pragma unroll
    for (int o = 16; o; o >>= 1) ss += __shfl_xor_sync(0xffffffffu, ss, o);

    __shared__ float ws[8];
    if ((t & 31) == 0) ws[grp * 4 + (t >> 5)] = ss;
    __syncthreads();
    float tot = ws[grp * 4] + ws[grp * 4 + 1] + ws[grp * 4 + 2] + ws[grp * 4 + 3];
    float scale = 1.0f / fmaxf(sqrtf(tot), 1e-8f);

    __half2 h0 = __floats2half2_rn(v0.x * scale, v0.y * scale);
    __half2 h1 = __floats2half2_rn(v0.z * scale, v0.w * scale);
    __half2 h2 = __floats2half2_rn(v1.x * scale, v1.y * scale);
    __half2 h3 = __floats2half2_rn(v1.z * scale, v1.w * scale);
    uint4 o;
    o.x = *reinterpret_cast<uint32_t*>(&h0);
    o.y = *reinterpret_cast<uint32_t*>(&h1);
    o.z = *reinterpret_cast<uint32_t*>(&h2);
    o.w = *reinterpret_cast<uint32_t*>(&h3);
    reinterpret_cast<uint4*>(dst + (size_t)row * DDIM)[t] = o;
}

// ============================================================================
// Kernel 2: fused GEMM + f16x2-exp + reductions + tail finalize
//   grid (64,64), block 128 (4 warps: 2(M) x 2(N); warp tile 64x64)
//   3-stage ring manually unrolled (period 3) -> compile-time slot addresses
// ============================================================================
__global__ void __launch_bounds__(NTHREADS, 2) gemm_loss_kernel(float* __restrict__ out) {
    extern __shared__ char smem[];
    const uint32_t sb = smem_to_u32(smem);
    const int tid  = threadIdx.x;
    const int wid  = tid >> 5;
    const int lane = tid & 31;
    const int warp_m = wid & 1;
    const int warp_n = wid >> 1;
    const int bi = blockIdx.y;
    const int bj = blockIdx.x;

    float* rowred = reinterpret_cast<float*>(smem + SM_ROWRED);
    float* colred = reinterpret_cast<float*>(smem + SM_COLRED);
    float* dsum   = reinterpret_cast<float*>(smem + SM_DIAG);
    unsigned int* lastf = reinterpret_cast<unsigned int*>(smem + SM_LAST);
    rowred[tid] = 0.0f;
    colred[tid] = 0.0f;
    if (tid == 0) dsum[0] = 0.0f;

    // ---- global load plan per stage: A 8 x 16B + B 8 x 16B per thread ----
    const uint4* Ag = reinterpret_cast<const uint4*>(g_imgn) + (size_t)bi * TILE * (DDIM / 8);
    const uint4* Bg = reinterpret_cast<const uint4*>(g_txtn) + (size_t)bj * TILE * (DDIM / 8);

    uint32_t sw_off[8];
    uint32_t gm_off[8];
#pragma unroll
    for (int i = 0; i < 8; i++) {
        int u = tid + NTHREADS * i;
        int row = u >> 3, c16 = u & 7;
        sw_off[i] = SMEM_SWIZZLE_128B((uint32_t)(row * 128 + c16 * 16));
        gm_off[i] = (uint32_t)(row * (DDIM / 8) + c16);
    }

    // ---- prologue: stages 0 and 1 ----
#pragma unroll
    for (int s = 0; s < 2; s++) {
        uint32_t sA = sb + s * STAGE_BYTES;
        uint32_t sB = sA + 16384;
#pragma unroll
        for (int i = 0; i < 8; i++) {
            cp_async16(sA + sw_off[i], Ag + gm_off[i] + s * 8);
            cp_async16(sB + sw_off[i], Bg + gm_off[i] + s * 8);
        }
        CP_ASYNC_COMMIT();
    }

    // ---- per-thread ldmatrix address components ----
    const uint32_t aRowByte = (uint32_t)((warp_m * 64 + (lane & 15)) * 128);
    const uint32_t aXor = (uint32_t)((lane & 7) << 4);
    const uint32_t aKB  = (uint32_t)((lane >> 4) * 16);
    const uint32_t bRowByte =
        (uint32_t)((warp_n * 64 + (lane & 7) + ((lane >> 4) & 1) * 8) * 128);
    const uint32_t bXor = (uint32_t)((lane & 7) << 4);
    const uint32_t bKB  = (uint32_t)(((lane >> 3) & 1) * 16);

    float acc[4][8][4];
#pragma unroll
    for (int mt = 0; mt < 4; mt++)
#pragma unroll
        for (int nt = 0; nt < 8; nt++)
#pragma unroll
            for (int e = 0; e < 4; e++) acc[mt][nt][e] = 0.0f;

    // ---- chunk body: compile-time slot constants sc (consume), sp (prefetch)
    auto chunk_body = [&](const int k, const int sc, const int sp) {
        CP_ASYNC_WAIT1();
        if (k == 0) {
            __syncthreads();
        } else {
            NBAR_SYNC(1 + ((k + 1) & 1));
        }
        const uint32_t sAs = sb + sc * STAGE_BYTES;
        const uint32_t sBs = sAs + 16384;
        const uint32_t sAp = sb + sp * STAGE_BYTES;
        const uint32_t sBp = sAp + 16384;
        const int kp = k + 2;
        const bool pf = (kp < NCHUNKS);

#pragma unroll
        for (int ks = 0; ks < 4; ks++) {
            const uint32_t kby = (uint32_t)(ks * 32);
            uint32_t a[4][4];
#pragma unroll
            for (int mt = 0; mt < 4; mt++)
                ldmatrix_x4(a[mt], sAs + aRowByte + (uint32_t)(mt * 16 * 128)
                            + ((kby + aKB) ^ aXor));
            uint32_t bf0[2][4];
#pragma unroll
            for (int p = 0; p < 2; p++)
                ldmatrix_x4(bf0[p], sBs + bRowByte + (uint32_t)(p * 16 * 128)
                            + ((kby + bKB) ^ bXor));
#pragma unroll
            for (int mt = 0; mt < 4; mt++)
#pragma unroll
                for (int q = 0; q < 4; q++) {
                    const uint32_t b0 = bf0[q >> 1][(q & 1) * 2 + 0];
                    const uint32_t b1 = bf0[q >> 1][(q & 1) * 2 + 1];
                    mma_f16_f32(acc[mt][q], a[mt], b0, b1);
                }
            uint32_t bf1[2][4];
#pragma unroll
            for (int p = 0; p < 2; p++)
                ldmatrix_x4(bf1[p], sBs + bRowByte + (uint32_t)((p + 2) * 16 * 128)
                            + ((kby + bKB) ^ bXor));
            if (ks == 3) NBAR_ARRIVE(1 + (k & 1));
            if (pf) {
                cp_async16(sAp + sw_off[ks], Ag + gm_off[ks] + kp * 8);
                cp_async16(sAp + sw_off[ks + 4], Ag + gm_off[ks + 4] + kp * 8);
                cp_async16(sBp + sw_off[ks], Bg + gm_off[ks] + kp * 8);
                cp_async16(sBp + sw_off[ks + 4], Bg + gm_off[ks + 4] + kp * 8);
            }
#pragma unroll
            for (int mt = 0; mt < 4; mt++)
#pragma unroll
                for (int q = 0; q < 4; q++) {
                    const uint32_t b0 = bf1[q >> 1][(q & 1) * 2 + 0];
                    const uint32_t b1 = bf1[q >> 1][(q & 1) * 2 + 1];
                    mma_f16_f32(acc[mt][q + 4], a[mt], b0, b1);
                }
        }
        CP_ASYNC_COMMIT();
    };

    // ---- mainloop: ring period 3 unrolled; 16 chunks = 5x3 + 1 tail ----
#pragma unroll 1
    for (int kk = 0; kk < NCHUNKS - 1; kk += 3) {
        chunk_body(kk,     0, 2);
        chunk_body(kk + 1, 1, 0);
        chunk_body(kk + 2, 2, 1);
    }
    chunk_body(NCHUNKS - 1, 0, 2);

    // ---- epilogue: f16x2 exp + reductions ----
    const int g  = lane >> 2;    // 0..7 : row within 8
    const int t4 = lane & 3;     // 0..3 : column pair selector
    const bool diagcta = (bi == bj);
    uint32_t rs0h[4] = {0, 0, 0, 0}, rs1h[4] = {0, 0, 0, 0};
    uint32_t colh[8] = {0, 0, 0, 0, 0, 0, 0, 0};
    float dloc = 0.0f;

#pragma unroll
    for (int mt = 0; mt < 4; mt++) {
#pragma unroll
        for (int nt = 0; nt < 8; nt++) {
            float d0 = acc[mt][nt][0], d1 = acc[mt][nt][1];
            float d2 = acc[mt][nt][2], d3 = acc[mt][nt][3];
            float a0 = fmaf(d0, K2E, C2);
            float a1 = fmaf(d1, K2E, C2);
            float a2 = fmaf(d2, K2E, C2);
            float a3 = fmaf(d3, K2E, C2);
            uint32_t e01 = ex2_f16x2(pack_f16x2(a0, a1));
            uint32_t e23 = ex2_f16x2(pack_f16x2(a2, a3));
            rs0h[mt] = hadd2u(rs0h[mt], e01);
            rs1h[mt] = hadd2u(rs1h[mt], e23);
            colh[nt] = hadd2u(colh[nt], hadd2u(e01, e23));
            if (diagcta) {
                int r0 = warp_m * 64 + mt * 16 + g;
                int c0 = warp_n * 64 + nt * 8 + 2 * t4;
                if (r0 == c0)         dloc += d0;
                if (r0 == c0 + 1)     dloc += d1;
                if (r0 + 8 == c0)     dloc += d2;
                if (r0 + 8 == c0 + 1) dloc += d3;
            }
        }
    }

#pragma unroll
    for (int mt = 0; mt < 4; mt++) {
        float2 f0 = h2_to_f2(rs0h[mt]);
        float2 f1 = h2_to_f2(rs1h[mt]);
        float v0 = f0.x + f0.y;
        float v1 = f1.x + f1.y;
        v0 += __shfl_xor_sync(0xffffffffu, v0, 1);
        v0 += __shfl_xor_sync(0xffffffffu, v0, 2);
        v1 += __shfl_xor_sync(0xffffffffu, v1, 1);
        v1 += __shfl_xor_sync(0xffffffffu, v1, 2);
        if (t4 == 0) {
            int r = warp_m * 64 + mt * 16 + g;
            atomicAdd(&rowred[r], v0);
            atomicAdd(&rowred[r + 8], v1);
        }
    }
#pragma unroll
    for (int nt = 0; nt < 8; nt++) {
        float2 fc = h2_to_f2(colh[nt]);
        float u0 = fc.x, u1 = fc.y;
        u0 += __shfl_xor_sync(0xffffffffu, u0, 4);
        u0 += __shfl_xor_sync(0xffffffffu, u0, 8);
        u0 += __shfl_xor_sync(0xffffffffu, u0, 16);
        u1 += __shfl_xor_sync(0xffffffffu, u1, 4);
        u1 += __shfl_xor_sync(0xffffffffu, u1, 8);
        u1 += __shfl_xor_sync(0xffffffffu, u1, 16);
        if (lane < 4) {
            int c = warp_n * 64 + nt * 8 + 2 * t4;
            atomicAdd(&colred[c], u0);
            atomicAdd(&colred[c + 1], u1);
        }
    }
    if (diagcta && dloc != 0.0f) atomicAdd(dsum, dloc);

    __syncthreads();
    atomicAdd(&g_rowsum[bi * TILE + tid], rowred[tid] * UNSHIFT);
    atomicAdd(&g_colsum[bj * TILE + tid], colred[tid] * UNSHIFT);
    if (diagcta && tid == 0) atomicAdd(&g_diag, dsum[0] * INV_T);

    // ---- last-CTA finalize + reset (graph-replay safe) ----
    __threadfence();
    if (tid == 0) lastf[0] = atomicAdd(&g_ctr, 1u);
    __syncthreads();
    if (lastf[0] == NCTAS - 1) {
        float accl = 0.0f;
        for (int i = tid; i < NROWS; i += NTHREADS)
            accl += logf(g_rowsum[i]) + logf(g_colsum[i]);
#pragma unroll
        for (int o = 16; o; o >>= 1) accl += __shfl_xor_sync(0xffffffffu, accl, o);
        if (lane == 0) colred[wid] = accl;
        __syncthreads();
        if (tid == 0) {
            float v = colred[0] + colred[1] + colred[2] + colred[3];
            out[0] = INV_T + 0.5f * v / (float)NROWS - g_diag / (float)NROWS;
            g_diag = 0.0f;
            g_ctr = 0u;
        }
        __syncthreads();
        for (int i = tid; i < NROWS; i += NTHREADS) {
            g_rowsum[i] = 0.0f;
            g_colsum[i] = 0.0f;
        }
    }
}

// ============================================================================
// Launch
// ============================================================================
extern "C" void kernel_launch(void* const* d_in, const int* in_sizes, int n_in,
                              void* d_out, int out_size) {
    const float* img = (const float*)d_in[0];
    const float* txt = (const float*)d_in[1];
    float* out = (float*)d_out;

    cudaFuncSetAttribute(gemm_loss_kernel,
                         cudaFuncAttributeMaxDynamicSharedMemorySize, SMEM_TOTAL);

    normalize_kernel<<<dim3(NROWS / 2, 2), 256>>>(img, txt);
    gemm_loss_kernel<<<dim3(NBLK, NBLK), NTHREADS, SMEM_TOTAL>>>(out);
}